// round 2
// baseline (speedup 1.0000x reference)
#include <cuda_runtime.h>
#include <cuda_fp16.h>
#include <cstdint>

// ============================================================================
// TernaryLinear: out[8192,4096] = x[8192,4096] @ (ternary(w)[4096,4096]).T
//
// Toolchain constraint (measured R1): PTX target is sm_103 (family baseline),
// so tcgen05.ld/st/wait are unavailable -> TMEM accumulators unreadable.
// Fallback: classic mma.sync (HMMA) fp16 GEMM with cp.async pipeline.
//
// Algebra: out = (x @ q^T) * scale[col], q in {-1,0,1} exact in fp16.
// Precision: x -> fp16 (u=2^-11) => norm rel err ~2.8e-4 < 1e-3. fp32 accum.
// ============================================================================

#define DINLINE __device__ __forceinline__

static constexpr int M = 8192, N = 4096, K = 4096;
static constexpr int BM = 128, BN = 256, BK = 64;
static constexpr int CHUNKS = K / BK;                 // 64
static constexpr int STAGE_BYTES = (BM + BN) * BK * 2; // 49152
static constexpr int SMEM_SIZE = 3 * STAGE_BYTES;      // 147456

// scratch (device globals: allocation-free)
__device__ __half g_q[(size_t)N * K];     // ternary weights, fp16 exact
__device__ __half g_xh[(size_t)M * K];    // x in fp16
__device__ float  g_scale[N];

// ---------------------------------------------------------------------------
// helpers
// ---------------------------------------------------------------------------
DINLINE uint32_t smem_u32(const void* p) {
    uint32_t a;
    asm("{ .reg .u64 t; cvta.to.shared.u64 t, %1; cvt.u32.u64 %0, t; }" : "=r"(a) : "l"(p));
    return a;
}
DINLINE void cp16(uint32_t dst, const void* src) {
    asm volatile("cp.async.cg.shared.global [%0], [%1], 16;" :: "r"(dst), "l"(src));
}
DINLINE void cp_commit() { asm volatile("cp.async.commit_group;" ::: "memory"); }
DINLINE void cp_wait1()  { asm volatile("cp.async.wait_group 1;" ::: "memory"); }

DINLINE void ldsm4(uint32_t* r, uint32_t addr) {
    asm volatile("ldmatrix.sync.aligned.m8n8.x4.shared.b16 {%0,%1,%2,%3}, [%4];"
                 : "=r"(r[0]), "=r"(r[1]), "=r"(r[2]), "=r"(r[3]) : "r"(addr));
}
DINLINE void mma16816(float* c, const uint32_t* a, const uint32_t* b) {
    asm volatile(
        "mma.sync.aligned.m16n8k16.row.col.f32.f16.f16.f32 "
        "{%0,%1,%2,%3}, {%4,%5,%6,%7}, {%8,%9}, {%0,%1,%2,%3};"
        : "+f"(c[0]), "+f"(c[1]), "+f"(c[2]), "+f"(c[3])
        : "r"(a[0]), "r"(a[1]), "r"(a[2]), "r"(a[3]), "r"(b[0]), "r"(b[1]));
}

// ---------------------------------------------------------------------------
// Prep kernels
// ---------------------------------------------------------------------------
__global__ void quantize_kernel(const float* __restrict__ w) {
    const int row = blockIdx.x, tid = threadIdx.x;
    const float4* wr = reinterpret_cast<const float4*>(w + (size_t)row * K);
    float s = 0.f;
    for (int i = tid; i < K / 4; i += 256) {
        float4 v = wr[i];
        s += fabsf(v.x) + fabsf(v.y) + fabsf(v.z) + fabsf(v.w);
    }
    for (int o = 16; o; o >>= 1) s += __shfl_xor_sync(~0u, s, o);
    __shared__ float warp_s[8];
    __shared__ float sc;
    if ((tid & 31) == 0) warp_s[tid >> 5] = s;
    __syncthreads();
    if (tid == 0) {
        float t = 0.f;
        for (int i = 0; i < 8; i++) t += warp_s[i];
        float m = t / (float)K;
        if (m < 1e-5f) m = 1e-5f;
        sc = m;
        g_scale[row] = m;
    }
    __syncthreads();
    const float scale = sc;
    __half2* qr = reinterpret_cast<__half2*>(g_q + (size_t)row * K);
    for (int i = tid; i < K / 4; i += 256) {
        float4 v = wr[i];
        float q0 = fminf(fmaxf(rintf(v.x / scale), -1.f), 1.f);
        float q1 = fminf(fmaxf(rintf(v.y / scale), -1.f), 1.f);
        float q2 = fminf(fmaxf(rintf(v.z / scale), -1.f), 1.f);
        float q3 = fminf(fmaxf(rintf(v.w / scale), -1.f), 1.f);
        qr[2 * i]     = __floats2half2_rn(q0, q1);
        qr[2 * i + 1] = __floats2half2_rn(q2, q3);
    }
}

__global__ void convert_kernel(const float* __restrict__ x) {
    size_t i = (size_t)blockIdx.x * 256 + threadIdx.x;   // processes 8 floats
    const float4* x4 = reinterpret_cast<const float4*>(x);
    float4 a = x4[2 * i], b = x4[2 * i + 1];
    __half2 h0 = __floats2half2_rn(a.x, a.y);
    __half2 h1 = __floats2half2_rn(a.z, a.w);
    __half2 h2 = __floats2half2_rn(b.x, b.y);
    __half2 h3 = __floats2half2_rn(b.z, b.w);
    uint4 o;
    o.x = *reinterpret_cast<uint32_t*>(&h0);
    o.y = *reinterpret_cast<uint32_t*>(&h1);
    o.z = *reinterpret_cast<uint32_t*>(&h2);
    o.w = *reinterpret_cast<uint32_t*>(&h3);
    reinterpret_cast<uint4*>(g_xh)[i] = o;
}

// ---------------------------------------------------------------------------
// GEMM: CTA 128x256, BK=64, 3-stage cp.async pipeline, 8 warps (2m x 4n),
// each warp 64x64 via mma.sync.m16n8k16. Smem rows = 64 halves (128B),
// xor swizzle: 16B-chunk index c -> c ^ (row & 7).
// ---------------------------------------------------------------------------
__global__ void __launch_bounds__(256, 1) gemm_kernel(
    const __half* __restrict__ A,   // [M,K] fp16
    const __half* __restrict__ B,   // [N,K] fp16 ternary
    float* __restrict__ out)        // [M,N] fp32
{
    extern __shared__ char smem[];
    const uint32_t sbase = smem_u32(smem);
    const int tid = threadIdx.x, lane = tid & 31, wid = tid >> 5;
    const int wm = wid >> 2, wn = wid & 3;     // warp tile: (wm*64, wn*64)
    const int mrow = blockIdx.y * BM;
    const int nbase = blockIdx.x * BN;

    float acc[4][8][4];
    #pragma unroll
    for (int i = 0; i < 4; i++)
        #pragma unroll
        for (int j = 0; j < 8; j++)
            #pragma unroll
            for (int k = 0; k < 4; k++) acc[i][j][k] = 0.f;

    // per-thread cp.async coordinates: 32 rows per iteration, 8 chunks/row
    const int ldrow = tid >> 3;          // 0..31
    const int ldc   = tid & 7;           // 16B chunk
    // ldmatrix lane coordinates
    const int arow = lane & 15, asel = lane >> 4;
    const int brow = (lane & 7) + ((lane >> 4) << 3), bsel = (lane >> 3) & 1;
    const int axor = arow & 7, bxor = brow & 7;

    auto load_stage = [&](int s, int kc) {
        const uint32_t sA = sbase + s * STAGE_BYTES;
        const uint32_t sB = sA + BM * 128;
        const size_t kof = (size_t)kc * BK + ldc * 8;
        #pragma unroll
        for (int it = 0; it < 4; it++) {
            const int row = it * 32 + ldrow;
            cp16(sA + row * 128 + ((ldc ^ (row & 7)) << 4),
                 A + (size_t)(mrow + row) * K + kof);
        }
        #pragma unroll
        for (int it = 0; it < 8; it++) {
            const int row = it * 32 + ldrow;
            cp16(sB + row * 128 + ((ldc ^ (row & 7)) << 4),
                 B + (size_t)(nbase + row) * K + kof);
        }
    };

    load_stage(0, 0); cp_commit();
    load_stage(1, 1); cp_commit();

    for (int i = 0; i < CHUNKS; i++) {
        cp_wait1();
        __syncthreads();
        if (i + 2 < CHUNKS) load_stage((i + 2) % 3, i + 2);
        cp_commit();

        const int s = i % 3;
        const uint32_t aB = sbase + s * STAGE_BYTES;
        const uint32_t bB = aB + BM * 128;
        #pragma unroll
        for (int ks = 0; ks < 4; ks++) {
            uint32_t af[4][4], bf[4][4];
            #pragma unroll
            for (int mt = 0; mt < 4; mt++) {
                const int row = wm * 64 + mt * 16 + arow;
                ldsm4(af[mt], aB + row * 128 + (((ks * 2 + asel) ^ axor) << 4));
            }
            #pragma unroll
            for (int p = 0; p < 4; p++) {
                const int row = wn * 64 + p * 16 + brow;
                ldsm4(bf[p], bB + row * 128 + (((ks * 2 + bsel) ^ bxor) << 4));
            }
            #pragma unroll
            for (int mt = 0; mt < 4; mt++)
                #pragma unroll
                for (int nt = 0; nt < 8; nt++)
                    mma16816(acc[mt][nt], af[mt], bf[nt >> 1] + (nt & 1) * 2);
        }
    }

    // epilogue: scale columns, write fp32
    const int g = lane >> 2, qn = lane & 3;
    #pragma unroll
    for (int nt = 0; nt < 8; nt++) {
        const int col = wn * 64 + nt * 8 + qn * 2;
        const float2 s2 = *reinterpret_cast<const float2*>(&g_scale[nbase + col]);
        #pragma unroll
        for (int mt = 0; mt < 4; mt++) {
            const int row0 = mrow + wm * 64 + mt * 16 + g;
            float2 v0 = { acc[mt][nt][0] * s2.x, acc[mt][nt][1] * s2.y };
            float2 v1 = { acc[mt][nt][2] * s2.x, acc[mt][nt][3] * s2.y };
            *reinterpret_cast<float2*>(out + (size_t)row0 * N + nbase + col) = v0;
            *reinterpret_cast<float2*>(out + (size_t)(row0 + 8) * N + nbase + col) = v1;
        }
    }
}

// ---------------------------------------------------------------------------
// Host launch
// ---------------------------------------------------------------------------
extern "C" void kernel_launch(void* const* d_in, const int* in_sizes, int n_in,
                              void* d_out, int out_size) {
    const float* x = (const float*)d_in[0];   // [8192, 4096]
    const float* w = (const float*)d_in[1];   // [4096, 4096]
    float* out = (float*)d_out;               // [8192, 4096]

    void *p_q = nullptr, *p_xh = nullptr;
    cudaGetSymbolAddress(&p_q, g_q);
    cudaGetSymbolAddress(&p_xh, g_xh);

    cudaFuncSetAttribute(gemm_kernel, cudaFuncAttributeMaxDynamicSharedMemorySize, SMEM_SIZE);

    quantize_kernel<<<N, 256>>>(w);
    convert_kernel<<<(int)(((size_t)M * K / 8) / 256), 256>>>(x);
    gemm_kernel<<<dim3(N / BN, M / BM), 256, SMEM_SIZE>>>(
        (const __half*)p_xh, (const __half*)p_q, out);
}

// round 3
// speedup vs baseline: 1.0383x; 1.0383x over previous
#include <cuda_runtime.h>
#include <cuda_fp16.h>
#include <cstdint>

// ============================================================================
// TernaryLinear: out[8192,4096] = x[8192,4096] @ (ternary(w)[4096,4096]).T
//
// out = (x @ q^T) * scale[col], q in {-1,0,1} exact in fp16; x -> fp16
// (u=2^-11 => ~3.5e-4 rel err, measured R2). fp32 accumulate in registers.
//
// R3: 4-stage cp.async pipeline + register frag double-buffering +
//     one-pass fused quantize/convert prep.
// ============================================================================

#define DINLINE __device__ __forceinline__

static constexpr int M = 8192, N = 4096, K = 4096;
static constexpr int BM = 128, BN = 256, BK = 64;
static constexpr int CHUNKS = K / BK;                  // 64
static constexpr int STAGES = 4;
static constexpr int STAGE_BYTES = (BM + BN) * BK * 2; // 49152
static constexpr int SMEM_SIZE = STAGES * STAGE_BYTES; // 196608

// scratch (device globals: allocation-free)
__device__ __half g_q[(size_t)N * K];     // ternary weights, fp16 exact
__device__ __half g_xh[(size_t)M * K];    // x in fp16
__device__ float  g_scale[N];

// ---------------------------------------------------------------------------
// helpers
// ---------------------------------------------------------------------------
DINLINE uint32_t smem_u32(const void* p) {
    uint32_t a;
    asm("{ .reg .u64 t; cvta.to.shared.u64 t, %1; cvt.u32.u64 %0, t; }" : "=r"(a) : "l"(p));
    return a;
}
DINLINE void cp16(uint32_t dst, const void* src) {
    asm volatile("cp.async.cg.shared.global [%0], [%1], 16;" :: "r"(dst), "l"(src));
}
DINLINE void cp_commit() { asm volatile("cp.async.commit_group;" ::: "memory"); }
DINLINE void cp_wait2()  { asm volatile("cp.async.wait_group 2;" ::: "memory"); }

DINLINE void ldsm4(uint32_t* r, uint32_t addr) {
    asm volatile("ldmatrix.sync.aligned.m8n8.x4.shared.b16 {%0,%1,%2,%3}, [%4];"
                 : "=r"(r[0]), "=r"(r[1]), "=r"(r[2]), "=r"(r[3]) : "r"(addr));
}
DINLINE void mma16816(float* c, const uint32_t* a, const uint32_t* b) {
    asm volatile(
        "mma.sync.aligned.m16n8k16.row.col.f32.f16.f16.f32 "
        "{%0,%1,%2,%3}, {%4,%5,%6,%7}, {%8,%9}, {%0,%1,%2,%3};"
        : "+f"(c[0]), "+f"(c[1]), "+f"(c[2]), "+f"(c[3])
        : "r"(a[0]), "r"(a[1]), "r"(a[2]), "r"(a[3]), "r"(b[0]), "r"(b[1]));
}

// ---------------------------------------------------------------------------
// Fused prep: blocks [0, N) quantize w rows (one-pass, row in registers);
// blocks [N, N + M*K/2048) convert x to fp16.
// ---------------------------------------------------------------------------
__global__ void __launch_bounds__(256) prep_kernel(const float* __restrict__ w,
                                                   const float* __restrict__ x) {
    if (blockIdx.x < (unsigned)N) {
        const int row = blockIdx.x, tid = threadIdx.x;
        const float4* wr = reinterpret_cast<const float4*>(w + (size_t)row * K);
        float4 v[4];
        float s = 0.f;
        #pragma unroll
        for (int t = 0; t < 4; t++) {
            v[t] = wr[tid + 256 * t];
            s += fabsf(v[t].x) + fabsf(v[t].y) + fabsf(v[t].z) + fabsf(v[t].w);
        }
        for (int o = 16; o; o >>= 1) s += __shfl_xor_sync(~0u, s, o);
        __shared__ float warp_s[8];
        __shared__ float sc;
        if ((tid & 31) == 0) warp_s[tid >> 5] = s;
        __syncthreads();
        if (tid == 0) {
            float t = 0.f;
            for (int i = 0; i < 8; i++) t += warp_s[i];
            float m = t * (1.f / (float)K);
            if (m < 1e-5f) m = 1e-5f;
            sc = m;
            g_scale[row] = m;
        }
        __syncthreads();
        const float inv = 1.f / sc;
        __half2* qr = reinterpret_cast<__half2*>(g_q + (size_t)row * K);
        #pragma unroll
        for (int t = 0; t < 4; t++) {
            float q0 = fminf(fmaxf(rintf(v[t].x * inv), -1.f), 1.f);
            float q1 = fminf(fmaxf(rintf(v[t].y * inv), -1.f), 1.f);
            float q2 = fminf(fmaxf(rintf(v[t].z * inv), -1.f), 1.f);
            float q3 = fminf(fmaxf(rintf(v[t].w * inv), -1.f), 1.f);
            qr[2 * (tid + 256 * t)]     = __floats2half2_rn(q0, q1);
            qr[2 * (tid + 256 * t) + 1] = __floats2half2_rn(q2, q3);
        }
    } else {
        size_t i = (size_t)(blockIdx.x - N) * 256 + threadIdx.x;  // 8 floats each
        const float4* x4 = reinterpret_cast<const float4*>(x);
        float4 a = x4[2 * i], b = x4[2 * i + 1];
        __half2 h0 = __floats2half2_rn(a.x, a.y);
        __half2 h1 = __floats2half2_rn(a.z, a.w);
        __half2 h2 = __floats2half2_rn(b.x, b.y);
        __half2 h3 = __floats2half2_rn(b.z, b.w);
        uint4 o;
        o.x = *reinterpret_cast<uint32_t*>(&h0);
        o.y = *reinterpret_cast<uint32_t*>(&h1);
        o.z = *reinterpret_cast<uint32_t*>(&h2);
        o.w = *reinterpret_cast<uint32_t*>(&h3);
        reinterpret_cast<uint4*>(g_xh)[i] = o;
    }
}

// ---------------------------------------------------------------------------
// GEMM: CTA 128x256, BK=64, 4-stage cp.async pipeline, 8 warps (2m x 4n),
// each warp 64x64 via mma.sync.m16n8k16 with register frag double-buffering.
// Smem rows = 64 halves (128B), xor swizzle: chunk c -> c ^ (row & 7).
// ---------------------------------------------------------------------------
__global__ void __launch_bounds__(256, 1) gemm_kernel(
    const __half* __restrict__ A,   // [M,K] fp16
    const __half* __restrict__ B,   // [N,K] fp16 ternary
    float* __restrict__ out)        // [M,N] fp32
{
    extern __shared__ char smem[];
    const uint32_t sbase = smem_u32(smem);
    const int tid = threadIdx.x, lane = tid & 31, wid = tid >> 5;
    const int wm = wid >> 2, wn = wid & 3;     // warp tile: (wm*64, wn*64)
    const int mrow = blockIdx.y * BM;
    const int nbase = blockIdx.x * BN;

    float acc[4][8][4];
    #pragma unroll
    for (int i = 0; i < 4; i++)
        #pragma unroll
        for (int j = 0; j < 8; j++)
            #pragma unroll
            for (int k = 0; k < 4; k++) acc[i][j][k] = 0.f;

    // cp.async coords: 32 rows/iter, 8 x 16B chunks per row
    const int ldrow = tid >> 3;
    const int ldc   = tid & 7;
    // ldmatrix lane coords
    const int arow = lane & 15, asel = lane >> 4;
    const int brow = (lane & 7) + ((lane >> 4) << 3), bsel = (lane >> 3) & 1;
    const int axor = arow & 7, bxor = brow & 7;

    auto load_stage = [&](int s, int kc) {
        const uint32_t sA = sbase + s * STAGE_BYTES;
        const uint32_t sB = sA + BM * 128;
        const size_t kof = (size_t)kc * BK + ldc * 8;
        #pragma unroll
        for (int it = 0; it < 4; it++) {
            const int row = it * 32 + ldrow;
            cp16(sA + row * 128 + ((ldc ^ (row & 7)) << 4),
                 A + (size_t)(mrow + row) * K + kof);
        }
        #pragma unroll
        for (int it = 0; it < 8; it++) {
            const int row = it * 32 + ldrow;
            cp16(sB + row * 128 + ((ldc ^ (row & 7)) << 4),
                 B + (size_t)(nbase + row) * K + kof);
        }
    };

    load_stage(0, 0); cp_commit();
    load_stage(1, 1); cp_commit();
    load_stage(2, 2); cp_commit();

    uint32_t af[2][4][4], bf[2][4][4];

    for (int i = 0; i < CHUNKS; i++) {
        cp_wait2();
        __syncthreads();
        if (i + 3 < CHUNKS) load_stage((i + 3) % STAGES, i + 3);
        cp_commit();

        const int s = i % STAGES;
        const uint32_t aB = sbase + s * STAGE_BYTES;
        const uint32_t bB = aB + BM * 128;

        auto load_frags = [&](int ks, int buf) {
            #pragma unroll
            for (int mt = 0; mt < 4; mt++) {
                const int row = wm * 64 + mt * 16 + arow;
                ldsm4(af[buf][mt], aB + row * 128 + (((ks * 2 + asel) ^ axor) << 4));
            }
            #pragma unroll
            for (int p = 0; p < 4; p++) {
                const int row = wn * 64 + p * 16 + brow;
                ldsm4(bf[buf][p], bB + row * 128 + (((ks * 2 + bsel) ^ bxor) << 4));
            }
        };

        load_frags(0, 0);
        #pragma unroll
        for (int ks = 0; ks < 4; ks++) {
            if (ks < 3) load_frags(ks + 1, (ks + 1) & 1);
            const int b = ks & 1;
            #pragma unroll
            for (int mt = 0; mt < 4; mt++)
                #pragma unroll
                for (int nt = 0; nt < 8; nt++)
                    mma16816(acc[mt][nt], af[b][mt], bf[b][nt >> 1] + (nt & 1) * 2);
        }
    }

    // epilogue: scale columns, write fp32
    const int g = lane >> 2, qn = lane & 3;
    #pragma unroll
    for (int nt = 0; nt < 8; nt++) {
        const int col = wn * 64 + nt * 8 + qn * 2;
        const float2 s2 = *reinterpret_cast<const float2*>(&g_scale[nbase + col]);
        #pragma unroll
        for (int mt = 0; mt < 4; mt++) {
            const int row0 = mrow + wm * 64 + mt * 16 + g;
            float2 v0 = { acc[mt][nt][0] * s2.x, acc[mt][nt][1] * s2.y };
            float2 v1 = { acc[mt][nt][2] * s2.x, acc[mt][nt][3] * s2.y };
            *reinterpret_cast<float2*>(out + (size_t)row0 * N + nbase + col) = v0;
            *reinterpret_cast<float2*>(out + (size_t)(row0 + 8) * N + nbase + col) = v1;
        }
    }
}

// ---------------------------------------------------------------------------
// Host launch
// ---------------------------------------------------------------------------
extern "C" void kernel_launch(void* const* d_in, const int* in_sizes, int n_in,
                              void* d_out, int out_size) {
    const float* x = (const float*)d_in[0];   // [8192, 4096]
    const float* w = (const float*)d_in[1];   // [4096, 4096]
    float* out = (float*)d_out;               // [8192, 4096]

    void *p_q = nullptr, *p_xh = nullptr;
    cudaGetSymbolAddress(&p_q, g_q);
    cudaGetSymbolAddress(&p_xh, g_xh);

    cudaFuncSetAttribute(gemm_kernel, cudaFuncAttributeMaxDynamicSharedMemorySize, SMEM_SIZE);

    const int conv_blocks = (int)(((size_t)M * K / 8) / 256);  // 16384
    prep_kernel<<<N + conv_blocks, 256>>>(w, x);
    gemm_kernel<<<dim3(N / BN, M / BM), 256, SMEM_SIZE>>>(
        (const __half*)p_xh, (const __half*)p_q, out);
}

// round 4
// speedup vs baseline: 1.2086x; 1.1641x over previous
#include <cuda_runtime.h>
#include <cuda_fp16.h>
#include <cstdint>

// ============================================================================
// TernaryLinear: out[8192,4096] = x[8192,4096] @ (ternary(w)[4096,4096]).T
//
// out = (x @ q^T) * scale[col], q in {-1,0,1} exact in fp16; x -> fp16
// (u=2^-11 => ~3.5e-4 rel err, measured). fp32 accumulate in registers.
//
// R4: cross-chunk ldmatrix prefetch. Pipeline guarantees stage i+1 resident
// at iteration i, so chunk i+1's first fragments are loaded before the
// barrier -> HMMAs issue immediately after sync (kills the 30% tensor-pipe
// bubble measured in R3).
// ============================================================================

#define DINLINE __device__ __forceinline__

static constexpr int M = 8192, N = 4096, K = 4096;
static constexpr int BM = 128, BN = 256, BK = 64;
static constexpr int CHUNKS = K / BK;                  // 64
static constexpr int STAGES = 4;
static constexpr int STAGE_BYTES = (BM + BN) * BK * 2; // 49152
static constexpr int SMEM_SIZE = STAGES * STAGE_BYTES; // 196608

// scratch (device globals: allocation-free)
__device__ __half g_q[(size_t)N * K];     // ternary weights, fp16 exact
__device__ __half g_xh[(size_t)M * K];    // x in fp16
__device__ float  g_scale[N];

// ---------------------------------------------------------------------------
// helpers
// ---------------------------------------------------------------------------
DINLINE uint32_t smem_u32(const void* p) {
    uint32_t a;
    asm("{ .reg .u64 t; cvta.to.shared.u64 t, %1; cvt.u32.u64 %0, t; }" : "=r"(a) : "l"(p));
    return a;
}
DINLINE void cp16(uint32_t dst, const void* src) {
    asm volatile("cp.async.cg.shared.global [%0], [%1], 16;" :: "r"(dst), "l"(src));
}
DINLINE void cp_commit() { asm volatile("cp.async.commit_group;" ::: "memory"); }
DINLINE void cp_wait1()  { asm volatile("cp.async.wait_group 1;" ::: "memory"); }
DINLINE void cp_wait2()  { asm volatile("cp.async.wait_group 2;" ::: "memory"); }

DINLINE void ldsm4(uint32_t* r, uint32_t addr) {
    asm volatile("ldmatrix.sync.aligned.m8n8.x4.shared.b16 {%0,%1,%2,%3}, [%4];"
                 : "=r"(r[0]), "=r"(r[1]), "=r"(r[2]), "=r"(r[3]) : "r"(addr));
}
DINLINE void mma16816(float* c, const uint32_t* a, const uint32_t* b) {
    asm volatile(
        "mma.sync.aligned.m16n8k16.row.col.f32.f16.f16.f32 "
        "{%0,%1,%2,%3}, {%4,%5,%6,%7}, {%8,%9}, {%0,%1,%2,%3};"
        : "+f"(c[0]), "+f"(c[1]), "+f"(c[2]), "+f"(c[3])
        : "r"(a[0]), "r"(a[1]), "r"(a[2]), "r"(a[3]), "r"(b[0]), "r"(b[1]));
}

// ---------------------------------------------------------------------------
// Fused prep: blocks [0, N) quantize w rows (one-pass, row in registers);
// blocks [N, N + M*K/2048) convert x to fp16.
// ---------------------------------------------------------------------------
__global__ void __launch_bounds__(256) prep_kernel(const float* __restrict__ w,
                                                   const float* __restrict__ x) {
    if (blockIdx.x < (unsigned)N) {
        const int row = blockIdx.x, tid = threadIdx.x;
        const float4* wr = reinterpret_cast<const float4*>(w + (size_t)row * K);
        float4 v[4];
        float s = 0.f;
        #pragma unroll
        for (int t = 0; t < 4; t++) {
            v[t] = wr[tid + 256 * t];
            s += fabsf(v[t].x) + fabsf(v[t].y) + fabsf(v[t].z) + fabsf(v[t].w);
        }
        for (int o = 16; o; o >>= 1) s += __shfl_xor_sync(~0u, s, o);
        __shared__ float warp_s[8];
        __shared__ float sc;
        if ((tid & 31) == 0) warp_s[tid >> 5] = s;
        __syncthreads();
        if (tid == 0) {
            float t = 0.f;
            for (int i = 0; i < 8; i++) t += warp_s[i];
            float m = t * (1.f / (float)K);
            if (m < 1e-5f) m = 1e-5f;
            sc = m;
            g_scale[row] = m;
        }
        __syncthreads();
        const float inv = 1.f / sc;
        __half2* qr = reinterpret_cast<__half2*>(g_q + (size_t)row * K);
        #pragma unroll
        for (int t = 0; t < 4; t++) {
            float q0 = fminf(fmaxf(rintf(v[t].x * inv), -1.f), 1.f);
            float q1 = fminf(fmaxf(rintf(v[t].y * inv), -1.f), 1.f);
            float q2 = fminf(fmaxf(rintf(v[t].z * inv), -1.f), 1.f);
            float q3 = fminf(fmaxf(rintf(v[t].w * inv), -1.f), 1.f);
            qr[2 * (tid + 256 * t)]     = __floats2half2_rn(q0, q1);
            qr[2 * (tid + 256 * t) + 1] = __floats2half2_rn(q2, q3);
        }
    } else {
        size_t i = (size_t)(blockIdx.x - N) * 256 + threadIdx.x;  // 8 floats each
        const float4* x4 = reinterpret_cast<const float4*>(x);
        float4 a = x4[2 * i], b = x4[2 * i + 1];
        __half2 h0 = __floats2half2_rn(a.x, a.y);
        __half2 h1 = __floats2half2_rn(a.z, a.w);
        __half2 h2 = __floats2half2_rn(b.x, b.y);
        __half2 h3 = __floats2half2_rn(b.z, b.w);
        uint4 o;
        o.x = *reinterpret_cast<uint32_t*>(&h0);
        o.y = *reinterpret_cast<uint32_t*>(&h1);
        o.z = *reinterpret_cast<uint32_t*>(&h2);
        o.w = *reinterpret_cast<uint32_t*>(&h3);
        reinterpret_cast<uint4*>(g_xh)[i] = o;
    }
}

// ---------------------------------------------------------------------------
// GEMM: CTA 128x256, BK=64, 4-stage cp.async pipeline, 8 warps (2m x 4n),
// each warp 64x64 via mma.sync.m16n8k16. Register frag double-buffering
// with CROSS-CHUNK prefetch: stage i+1 is guaranteed resident at iter i
// (wait_group 1), so ks=3 prefetches chunk i+1's ks=0 fragments.
// Smem rows = 64 halves (128B), xor swizzle: chunk c -> c ^ (row & 7).
// ---------------------------------------------------------------------------
__global__ void __launch_bounds__(256, 1) gemm_kernel(
    const __half* __restrict__ A,   // [M,K] fp16
    const __half* __restrict__ B,   // [N,K] fp16 ternary
    float* __restrict__ out)        // [M,N] fp32
{
    extern __shared__ char smem[];
    const uint32_t sbase = smem_u32(smem);
    const int tid = threadIdx.x, lane = tid & 31, wid = tid >> 5;
    const int wm = wid >> 2, wn = wid & 3;     // warp tile: (wm*64, wn*64)
    const int mrow = blockIdx.y * BM;
    const int nbase = blockIdx.x * BN;

    float acc[4][8][4];
    #pragma unroll
    for (int i = 0; i < 4; i++)
        #pragma unroll
        for (int j = 0; j < 8; j++)
            #pragma unroll
            for (int k = 0; k < 4; k++) acc[i][j][k] = 0.f;

    // cp.async coords: 32 rows/iter, 8 x 16B chunks per row
    const int ldrow = tid >> 3;
    const int ldc   = tid & 7;
    // ldmatrix lane coords
    const int arow = lane & 15, asel = lane >> 4;
    const int brow = (lane & 7) + ((lane >> 4) << 3), bsel = (lane >> 3) & 1;
    const int axor = arow & 7, bxor = brow & 7;

    auto load_stage = [&](int s, int kc) {
        const uint32_t sA = sbase + s * STAGE_BYTES;
        const uint32_t sB = sA + BM * 128;
        const size_t kof = (size_t)kc * BK + ldc * 8;
        #pragma unroll
        for (int it = 0; it < 4; it++) {
            const int row = it * 32 + ldrow;
            cp16(sA + row * 128 + ((ldc ^ (row & 7)) << 4),
                 A + (size_t)(mrow + row) * K + kof);
        }
        #pragma unroll
        for (int it = 0; it < 8; it++) {
            const int row = it * 32 + ldrow;
            cp16(sB + row * 128 + ((ldc ^ (row & 7)) << 4),
                 B + (size_t)(nbase + row) * K + kof);
        }
    };

    uint32_t af[2][4][4], bf[2][4][4];

    auto load_frags = [&](uint32_t aB, uint32_t bB, int ks, int buf) {
        #pragma unroll
        for (int mt = 0; mt < 4; mt++) {
            const int row = wm * 64 + mt * 16 + arow;
            ldsm4(af[buf][mt], aB + row * 128 + (((ks * 2 + asel) ^ axor) << 4));
        }
        #pragma unroll
        for (int p = 0; p < 4; p++) {
            const int row = wn * 64 + p * 16 + brow;
            ldsm4(bf[buf][p], bB + row * 128 + (((ks * 2 + bsel) ^ bxor) << 4));
        }
    };

    // prologue: 3 chunks in flight; make stage 0 visible, prefetch frags(0,0)
    load_stage(0, 0); cp_commit();
    load_stage(1, 1); cp_commit();
    load_stage(2, 2); cp_commit();
    cp_wait2();
    __syncthreads();
    load_frags(sbase, sbase + BM * 128, 0, 0);

    for (int i = 0; i < CHUNKS; i++) {
        // chunks <= i+1 complete; barrier publishes them to all warps
        cp_wait1();
        __syncthreads();
        if (i + 3 < CHUNKS) load_stage((i + 3) % STAGES, i + 3);
        cp_commit();

        const uint32_t aB = sbase + (i % STAGES) * STAGE_BYTES;
        const uint32_t bB = aB + BM * 128;
        const uint32_t aBn = sbase + ((i + 1) % STAGES) * STAGE_BYTES;
        const uint32_t bBn = aBn + BM * 128;

        #pragma unroll
        for (int ks = 0; ks < 4; ks++) {
            const int b = ks & 1;
            if (ks < 3)                load_frags(aB,  bB,  ks + 1, b ^ 1);
            else if (i + 1 < CHUNKS)   load_frags(aBn, bBn, 0,      b ^ 1);
            #pragma unroll
            for (int mt = 0; mt < 4; mt++)
                #pragma unroll
                for (int nt = 0; nt < 8; nt++)
                    mma16816(acc[mt][nt], af[b][mt], bf[b][nt >> 1] + (nt & 1) * 2);
        }
    }

    // epilogue: scale columns, write fp32
    const int g = lane >> 2, qn = lane & 3;
    #pragma unroll
    for (int nt = 0; nt < 8; nt++) {
        const int col = wn * 64 + nt * 8 + qn * 2;
        const float2 s2 = *reinterpret_cast<const float2*>(&g_scale[nbase + col]);
        #pragma unroll
        for (int mt = 0; mt < 4; mt++) {
            const int row0 = mrow + wm * 64 + mt * 16 + g;
            float2 v0 = { acc[mt][nt][0] * s2.x, acc[mt][nt][1] * s2.y };
            float2 v1 = { acc[mt][nt][2] * s2.x, acc[mt][nt][3] * s2.y };
            *reinterpret_cast<float2*>(out + (size_t)row0 * N + nbase + col) = v0;
            *reinterpret_cast<float2*>(out + (size_t)(row0 + 8) * N + nbase + col) = v1;
        }
    }
}

// ---------------------------------------------------------------------------
// Host launch
// ---------------------------------------------------------------------------
extern "C" void kernel_launch(void* const* d_in, const int* in_sizes, int n_in,
                              void* d_out, int out_size) {
    const float* x = (const float*)d_in[0];   // [8192, 4096]
    const float* w = (const float*)d_in[1];   // [4096, 4096]
    float* out = (float*)d_out;               // [8192, 4096]

    void *p_q = nullptr, *p_xh = nullptr;
    cudaGetSymbolAddress(&p_q, g_q);
    cudaGetSymbolAddress(&p_xh, g_xh);

    cudaFuncSetAttribute(gemm_kernel, cudaFuncAttributeMaxDynamicSharedMemorySize, SMEM_SIZE);

    const int conv_blocks = (int)(((size_t)M * K / 8) / 256);  // 16384
    prep_kernel<<<N + conv_blocks, 256>>>(w, x);
    gemm_kernel<<<dim3(N / BN, M / BM), 256, SMEM_SIZE>>>(
        (const __half*)p_xh, (const __half*)p_q, out);
}

// round 5
// speedup vs baseline: 1.2329x; 1.0201x over previous
#include <cuda_runtime.h>
#include <cuda_fp16.h>
#include <cstdint>

// ============================================================================
// TernaryLinear: out[8192,4096] = x[8192,4096] @ (ternary(w)[4096,4096]).T
//
// out = (x @ q^T) * scale[col], q in {-1,0,1} exact in fp16; x -> fp16
// (u=2^-11 => ~3.5e-4 rel err, measured). fp32 accumulate in registers.
//
// R5: 2 CTAs/SM x 128 threads, 128x128 tiles, 3-stage pipeline. Each SMSP
// now runs 2 warps from INDEPENDENT CTAs, so per-CTA barriers no longer
// idle the tensor pipe (R4 measured 82.4% tensor with correlated barriers).
// Per-warp inner loop identical to R4 (64x64 warp tile, cross-chunk
// ldmatrix prefetch, register frag double-buffering).
// ============================================================================

#define DINLINE __device__ __forceinline__

static constexpr int M = 8192, N = 4096, K = 4096;
static constexpr int BM = 128, BN = 128, BK = 64;
static constexpr int CHUNKS = K / BK;                  // 64
static constexpr int STAGES = 3;
static constexpr int STAGE_BYTES = (BM + BN) * BK * 2; // 32768
static constexpr int SMEM_SIZE = STAGES * STAGE_BYTES; // 98304

// scratch (device globals: allocation-free)
__device__ __half g_q[(size_t)N * K];     // ternary weights, fp16 exact
__device__ __half g_xh[(size_t)M * K];    // x in fp16
__device__ float  g_scale[N];

// ---------------------------------------------------------------------------
// helpers
// ---------------------------------------------------------------------------
DINLINE uint32_t smem_u32(const void* p) {
    uint32_t a;
    asm("{ .reg .u64 t; cvta.to.shared.u64 t, %1; cvt.u32.u64 %0, t; }" : "=r"(a) : "l"(p));
    return a;
}
DINLINE void cp16(uint32_t dst, const void* src) {
    asm volatile("cp.async.cg.shared.global [%0], [%1], 16;" :: "r"(dst), "l"(src));
}
DINLINE void cp_commit() { asm volatile("cp.async.commit_group;" ::: "memory"); }
DINLINE void cp_wait0()  { asm volatile("cp.async.wait_group 0;" ::: "memory"); }
DINLINE void cp_wait1()  { asm volatile("cp.async.wait_group 1;" ::: "memory"); }

DINLINE void ldsm4(uint32_t* r, uint32_t addr) {
    asm volatile("ldmatrix.sync.aligned.m8n8.x4.shared.b16 {%0,%1,%2,%3}, [%4];"
                 : "=r"(r[0]), "=r"(r[1]), "=r"(r[2]), "=r"(r[3]) : "r"(addr));
}
DINLINE void mma16816(float* c, const uint32_t* a, const uint32_t* b) {
    asm volatile(
        "mma.sync.aligned.m16n8k16.row.col.f32.f16.f16.f32 "
        "{%0,%1,%2,%3}, {%4,%5,%6,%7}, {%8,%9}, {%0,%1,%2,%3};"
        : "+f"(c[0]), "+f"(c[1]), "+f"(c[2]), "+f"(c[3])
        : "r"(a[0]), "r"(a[1]), "r"(a[2]), "r"(a[3]), "r"(b[0]), "r"(b[1]));
}

// ---------------------------------------------------------------------------
// Fused prep: blocks [0, N) quantize w rows (one-pass, row in registers);
// blocks [N, N + M*K/2048) convert x to fp16.
// ---------------------------------------------------------------------------
__global__ void __launch_bounds__(256) prep_kernel(const float* __restrict__ w,
                                                   const float* __restrict__ x) {
    if (blockIdx.x < (unsigned)N) {
        const int row = blockIdx.x, tid = threadIdx.x;
        const float4* wr = reinterpret_cast<const float4*>(w + (size_t)row * K);
        float4 v[4];
        float s = 0.f;
        #pragma unroll
        for (int t = 0; t < 4; t++) {
            v[t] = wr[tid + 256 * t];
            s += fabsf(v[t].x) + fabsf(v[t].y) + fabsf(v[t].z) + fabsf(v[t].w);
        }
        for (int o = 16; o; o >>= 1) s += __shfl_xor_sync(~0u, s, o);
        __shared__ float warp_s[8];
        __shared__ float sc;
        if ((tid & 31) == 0) warp_s[tid >> 5] = s;
        __syncthreads();
        if (tid == 0) {
            float t = 0.f;
            for (int i = 0; i < 8; i++) t += warp_s[i];
            float m = t * (1.f / (float)K);
            if (m < 1e-5f) m = 1e-5f;
            sc = m;
            g_scale[row] = m;
        }
        __syncthreads();
        const float inv = 1.f / sc;
        __half2* qr = reinterpret_cast<__half2*>(g_q + (size_t)row * K);
        #pragma unroll
        for (int t = 0; t < 4; t++) {
            float q0 = fminf(fmaxf(rintf(v[t].x * inv), -1.f), 1.f);
            float q1 = fminf(fmaxf(rintf(v[t].y * inv), -1.f), 1.f);
            float q2 = fminf(fmaxf(rintf(v[t].z * inv), -1.f), 1.f);
            float q3 = fminf(fmaxf(rintf(v[t].w * inv), -1.f), 1.f);
            qr[2 * (tid + 256 * t)]     = __floats2half2_rn(q0, q1);
            qr[2 * (tid + 256 * t) + 1] = __floats2half2_rn(q2, q3);
        }
    } else {
        size_t i = (size_t)(blockIdx.x - N) * 256 + threadIdx.x;  // 8 floats each
        const float4* x4 = reinterpret_cast<const float4*>(x);
        float4 a = x4[2 * i], b = x4[2 * i + 1];
        __half2 h0 = __floats2half2_rn(a.x, a.y);
        __half2 h1 = __floats2half2_rn(a.z, a.w);
        __half2 h2 = __floats2half2_rn(b.x, b.y);
        __half2 h3 = __floats2half2_rn(b.z, b.w);
        uint4 o;
        o.x = *reinterpret_cast<uint32_t*>(&h0);
        o.y = *reinterpret_cast<uint32_t*>(&h1);
        o.z = *reinterpret_cast<uint32_t*>(&h2);
        o.w = *reinterpret_cast<uint32_t*>(&h3);
        reinterpret_cast<uint4*>(g_xh)[i] = o;
    }
}

// ---------------------------------------------------------------------------
// GEMM: CTA 128x128, BK=64, 3-stage cp.async pipeline, 4 warps (2m x 2n),
// 2 CTAs per SM. Warp tile 64x64 via mma.sync.m16n8k16, register frag
// double-buffering with cross-chunk prefetch (stage i+1 resident at iter i).
// Smem rows = 64 halves (128B), xor swizzle: chunk c -> c ^ (row & 7).
// ---------------------------------------------------------------------------
__global__ void __launch_bounds__(128, 2) gemm_kernel(
    const __half* __restrict__ A,   // [M,K] fp16
    const __half* __restrict__ B,   // [N,K] fp16 ternary
    float* __restrict__ out)        // [M,N] fp32
{
    extern __shared__ char smem[];
    const uint32_t sbase = smem_u32(smem);
    const int tid = threadIdx.x, lane = tid & 31, wid = tid >> 5;
    const int wm = wid >> 1, wn = wid & 1;     // warp tile: (wm*64, wn*64)
    const int mrow = blockIdx.y * BM;
    const int nbase = blockIdx.x * BN;

    float acc[4][8][4];
    #pragma unroll
    for (int i = 0; i < 4; i++)
        #pragma unroll
        for (int j = 0; j < 8; j++)
            #pragma unroll
            for (int k = 0; k < 4; k++) acc[i][j][k] = 0.f;

    // cp.async coords: 16 rows/iter across 128 threads, 8 x 16B chunks per row
    const int ldrow = tid >> 3;          // 0..15
    const int ldc   = tid & 7;
    // ldmatrix lane coords
    const int arow = lane & 15, asel = lane >> 4;
    const int brow = (lane & 7) + ((lane >> 4) << 3), bsel = (lane >> 3) & 1;
    const int axor = arow & 7, bxor = brow & 7;

    auto load_stage = [&](int s, int kc) {
        const uint32_t sA = sbase + s * STAGE_BYTES;
        const uint32_t sB = sA + BM * 128;
        const size_t kof = (size_t)kc * BK + ldc * 8;
        #pragma unroll
        for (int it = 0; it < 8; it++) {
            const int row = it * 16 + ldrow;
            cp16(sA + row * 128 + ((ldc ^ (row & 7)) << 4),
                 A + (size_t)(mrow + row) * K + kof);
        }
        #pragma unroll
        for (int it = 0; it < 8; it++) {
            const int row = it * 16 + ldrow;
            cp16(sB + row * 128 + ((ldc ^ (row & 7)) << 4),
                 B + (size_t)(nbase + row) * K + kof);
        }
    };

    uint32_t af[2][4][4], bf[2][4][4];

    auto load_frags = [&](uint32_t aB, uint32_t bB, int ks, int buf) {
        #pragma unroll
        for (int mt = 0; mt < 4; mt++) {
            const int row = wm * 64 + mt * 16 + arow;
            ldsm4(af[buf][mt], aB + row * 128 + (((ks * 2 + asel) ^ axor) << 4));
        }
        #pragma unroll
        for (int p = 0; p < 4; p++) {
            const int row = wn * 64 + p * 16 + brow;
            ldsm4(bf[buf][p], bB + row * 128 + (((ks * 2 + bsel) ^ bxor) << 4));
        }
    };

    // prologue: chunks 0,1 in flight; publish stage 0; prefetch frags(0,0)
    load_stage(0, 0); cp_commit();
    load_stage(1, 1); cp_commit();
    cp_wait1();
    __syncthreads();
    load_frags(sbase, sbase + BM * 128, 0, 0);

    for (int i = 0; i < CHUNKS; i++) {
        // all committed groups (chunks <= i+1) complete; barrier publishes
        cp_wait0();
        __syncthreads();
        if (i + 2 < CHUNKS) { load_stage((i + 2) % STAGES, i + 2); cp_commit(); }

        const uint32_t aB = sbase + (i % STAGES) * STAGE_BYTES;
        const uint32_t bB = aB + BM * 128;
        const uint32_t aBn = sbase + ((i + 1) % STAGES) * STAGE_BYTES;
        const uint32_t bBn = aBn + BM * 128;

        #pragma unroll
        for (int ks = 0; ks < 4; ks++) {
            const int b = ks & 1;
            if (ks < 3)                load_frags(aB,  bB,  ks + 1, b ^ 1);
            else if (i + 1 < CHUNKS)   load_frags(aBn, bBn, 0,      b ^ 1);
            #pragma unroll
            for (int mt = 0; mt < 4; mt++)
                #pragma unroll
                for (int nt = 0; nt < 8; nt++)
                    mma16816(acc[mt][nt], af[b][mt], bf[b][nt >> 1] + (nt & 1) * 2);
        }
    }

    // epilogue: scale columns, write fp32
    const int g = lane >> 2, qn = lane & 3;
    #pragma unroll
    for (int nt = 0; nt < 8; nt++) {
        const int col = wn * 64 + nt * 8 + qn * 2;
        const float2 s2 = *reinterpret_cast<const float2*>(&g_scale[nbase + col]);
        #pragma unroll
        for (int mt = 0; mt < 4; mt++) {
            const int row0 = mrow + wm * 64 + mt * 16 + g;
            float2 v0 = { acc[mt][nt][0] * s2.x, acc[mt][nt][1] * s2.y };
            float2 v1 = { acc[mt][nt][2] * s2.x, acc[mt][nt][3] * s2.y };
            *reinterpret_cast<float2*>(out + (size_t)row0 * N + nbase + col) = v0;
            *reinterpret_cast<float2*>(out + (size_t)(row0 + 8) * N + nbase + col) = v1;
        }
    }
}

// ---------------------------------------------------------------------------
// Host launch
// ---------------------------------------------------------------------------
extern "C" void kernel_launch(void* const* d_in, const int* in_sizes, int n_in,
                              void* d_out, int out_size) {
    const float* x = (const float*)d_in[0];   // [8192, 4096]
    const float* w = (const float*)d_in[1];   // [4096, 4096]
    float* out = (float*)d_out;               // [8192, 4096]

    void *p_q = nullptr, *p_xh = nullptr;
    cudaGetSymbolAddress(&p_q, g_q);
    cudaGetSymbolAddress(&p_xh, g_xh);

    cudaFuncSetAttribute(gemm_kernel, cudaFuncAttributeMaxDynamicSharedMemorySize, SMEM_SIZE);

    const int conv_blocks = (int)(((size_t)M * K / 8) / 256);  // 16384
    prep_kernel<<<N + conv_blocks, 256>>>(w, x);
    gemm_kernel<<<dim3(N / BN, M / BM), 128, SMEM_SIZE>>>(
        (const __half*)p_xh, (const __half*)p_q, out);
}